// round 12
// baseline (speedup 1.0000x reference)
#include <cuda_runtime.h>
#include <cuda_fp16.h>
#include <cstdint>

// ---------------- problem dims ----------------
#define IN_F   2048
#define OUT_F  2048
#define BATCH  8192
#define GDIM   8
#define KTOT   (2 * IN_F)          // 4096 concat K

// ---------------- GEMM config -----------------
#define BM      64
#define BN      128
#define BK      64                 // halves per chunk (128 B per row)
#define STAGES  3
#define THREADS 128                // 4 warps, 2x2 grid of 32x64 warp tiles
#define NCHUNKS (KTOT / BK)        // 64
#define PITCH_B 144                // bytes per smem row (128 data + 16 pad)
#define TILEA_B (BM * PITCH_B)     // 9216 B
#define TILEB_B (BN * PITCH_B)     // 18432 B
#define STAGE_B (TILEA_B + TILEB_B)            // 27648 B
#define SMEM_BYTES (STAGES * STAGE_B)          // 82944

// ---------------- device scratch ----------------
__device__ __half g_acat[(size_t)BATCH * KTOT];  // [b][ x | basis ] fp16
__device__ __half g_bcat[(size_t)OUT_F * KTOT];  // [n][ w1 | gsumT ] fp16
__device__ float g_partials[4096];
__device__ float g_mean;

// ---------------- helpers ----------------
__device__ __forceinline__ uint32_t smem_u32(const void* p) {
    uint32_t a;
    asm("{ .reg .u64 t; cvta.to.shared.u64 t, %1; cvt.u32.u64 %0, t; }"
        : "=r"(a) : "l"(p));
    return a;
}

__device__ __forceinline__ void cp16(uint32_t dst, const void* src) {
    asm volatile("cp.async.cg.shared.global [%0], [%1], 16;"
                 :: "r"(dst), "l"(src));
}
#define CP_COMMIT() asm volatile("cp.async.commit_group;" ::: "memory")
#define CP_WAIT1()  asm volatile("cp.async.wait_group 1;" ::: "memory")

__device__ __forceinline__ void ldsm_x4(uint32_t& r0, uint32_t& r1,
                                        uint32_t& r2, uint32_t& r3, uint32_t addr) {
    asm volatile("ldmatrix.sync.aligned.m8n8.x4.shared.b16 {%0,%1,%2,%3}, [%4];"
                 : "=r"(r0), "=r"(r1), "=r"(r2), "=r"(r3) : "r"(addr));
}

__device__ __forceinline__ void mma_f16(float* c,
                                        uint32_t a0, uint32_t a1, uint32_t a2, uint32_t a3,
                                        uint32_t b0, uint32_t b1) {
    asm volatile(
        "mma.sync.aligned.m16n8k16.row.col.f32.f16.f16.f32 "
        "{%0,%1,%2,%3}, {%4,%5,%6,%7}, {%8,%9}, {%0,%1,%2,%3};"
        : "+f"(c[0]), "+f"(c[1]), "+f"(c[2]), "+f"(c[3])
        : "r"(a0), "r"(a1), "r"(a2), "r"(a3), "r"(b0), "r"(b1));
}

// ---------------- kernel 1: grid reduce + transpose into g_bcat + partials ----
__global__ void __launch_bounds__(1024) k_prep(const float* __restrict__ grid) {
    __shared__ float tile[32][33];
    __shared__ float wsum[32];
    int tx = threadIdx.x, ty = threadIdx.y;
    int i = blockIdx.y * 32 + ty;   // in-feature
    int o = blockIdx.x * 32 + tx;   // out-feature
    const float4* p = reinterpret_cast<const float4*>(grid + ((size_t)i * OUT_F + o) * GDIM);
    float4 a = p[0], b = p[1];
    float s = ((a.x + a.y) + (a.z + a.w)) + ((b.x + b.y) + (b.z + b.w));
    tile[ty][tx] = s;
    float r = s;
    #pragma unroll
    for (int off = 16; off > 0; off >>= 1)
        r += __shfl_xor_sync(0xFFFFFFFFu, r, off);
    if (tx == 0) wsum[ty] = r;
    __syncthreads();
    if (ty == 0) {
        float w = wsum[tx];
        #pragma unroll
        for (int off = 16; off > 0; off >>= 1)
            w += __shfl_xor_sync(0xFFFFFFFFu, w, off);
        if (tx == 0) g_partials[blockIdx.y * gridDim.x + blockIdx.x] = w;
    }
    // transposed fp16 write into concat-B upper half: bcat[o][2048 + i]
    float v = tile[tx][ty];
    int oo = blockIdx.x * 32 + ty;
    int ii = blockIdx.y * 32 + tx;
    g_bcat[(size_t)oo * KTOT + IN_F + ii] = __float2half_rn(v);
}

// ---------------- kernel 2: final mean ----------------
__global__ void __launch_bounds__(1024) k_mean() {
    __shared__ float red[1024];
    int t = threadIdx.x;
    red[t] = g_partials[t] + g_partials[t + 1024] + g_partials[t + 2048] + g_partials[t + 3072];
    __syncthreads();
    #pragma unroll
    for (int off = 512; off > 0; off >>= 1) {
        if (t < off) red[t] += red[t + off];
        __syncthreads();
    }
    if (t == 0) g_mean = red[0] * (1.0f / ((float)IN_F * (float)OUT_F * (float)GDIM));
}

// ---------------- kernel 3: w1 -> fp16 into g_bcat lower half ----------------
__global__ void __launch_bounds__(256) k_wcvt(const float* __restrict__ w1) {
    size_t idx = (size_t)blockIdx.x * 256 + threadIdx.x;   // float4 index
    const float4 f = reinterpret_cast<const float4*>(w1)[idx];
    size_t n = idx / (IN_F / 4);
    size_t k4 = idx % (IN_F / 4);
    __half2 h0 = make_half2(__float2half_rn(f.x), __float2half_rn(f.y));
    __half2 h1 = make_half2(__float2half_rn(f.z), __float2half_rn(f.w));
    *reinterpret_cast<__half2*>(g_bcat + n * KTOT + k4 * 4)     = h0;
    *reinterpret_cast<__half2*>(g_bcat + n * KTOT + k4 * 4 + 2) = h1;
}

// ---------------- kernel 4: x -> fp16 + basis -> g_acat ----------------
__global__ void __launch_bounds__(256) k_xbasis(const float* __restrict__ x) {
    const float gmean = g_mean;
    size_t idx = (size_t)blockIdx.x * 256 + threadIdx.x;   // float4 index
    const float4 f = reinterpret_cast<const float4*>(x)[idx];
    size_t b = idx / (IN_F / 4);
    size_t k4 = idx % (IN_F / 4);
    __half* dst = g_acat + b * KTOT;
    *reinterpret_cast<__half2*>(dst + k4 * 4) =
        make_half2(__float2half_rn(f.x), __float2half_rn(f.y));
    *reinterpret_cast<__half2*>(dst + k4 * 4 + 2) =
        make_half2(__float2half_rn(f.z), __float2half_rn(f.w));
    float d0 = f.x - gmean, d1 = f.y - gmean, d2 = f.z - gmean, d3 = f.w - gmean;
    *reinterpret_cast<__half2*>(dst + IN_F + k4 * 4) =
        make_half2(__float2half_rn(__expf(-d0 * d0)), __float2half_rn(__expf(-d1 * d1)));
    *reinterpret_cast<__half2*>(dst + IN_F + k4 * 4 + 2) =
        make_half2(__float2half_rn(__expf(-d2 * d2)), __float2half_rn(__expf(-d3 * d3)));
}

// ---------------- kernel 5: fp16 GEMM, CTA 64x128, 4 warps of 32x64, x2/SM ----
// out[m][n] = sum_k acat[m][k] * bcat[n][k]
__global__ void __launch_bounds__(THREADS, 2)
k_gemm(float* __restrict__ out) {
    extern __shared__ char smem[];
    const uint32_t sbase = smem_u32(smem);
    const int tid  = threadIdx.x;
    const int warp = tid >> 5;
    const int lane = tid & 31;
    const int grp  = lane >> 2;   // 0..7
    const int tig  = lane & 3;    // 0..3
    const int warp_m = warp >> 1; // 0..1  (32-row slab)
    const int warp_n = warp & 1;  // 0..1  (64-col slab)

    const int m0 = blockIdx.y * BM;
    const int n0 = blockIdx.x * BN;

    const __half* ag = g_acat + (size_t)m0 * KTOT;
    const __half* bg = g_bcat + (size_t)n0 * KTOT;

    float acc[2][8][4];
    #pragma unroll
    for (int mi = 0; mi < 2; ++mi)
        #pragma unroll
        for (int ni = 0; ni < 8; ++ni)
            #pragma unroll
            for (int j = 0; j < 4; ++j) acc[mi][ni][j] = 0.f;

    // ldmatrix lane address components (all non-trans)
    const int rowA = warp_m * 32 + (lane & 7) + ((lane >> 3) & 1) * 8;
    const uint32_t colA = ((lane >> 4) & 1) * 16;
    const int rowB = warp_n * 64 + (lane & 7) + ((lane >> 4) & 1) * 8;
    const uint32_t colB = ((lane >> 3) & 1) * 16;

    // loader: A = 64 rows x 8 chunks = 512 (4/thread), B = 128 x 8 = 1024 (8/thread)
    const int lrow = tid >> 3;        // 0..15, +16 per step
    const int lch  = tid & 7;         // 16B chunk within 128B row

    auto issue_stage = [&](int kc) {
        const int st = kc % STAGES;
        const uint32_t stA = sbase + (uint32_t)(st * STAGE_B);
        const uint32_t stB = stA + TILEA_B;
        const int k0 = kc * BK;
        #pragma unroll
        for (int i = 0; i < 4; ++i) {
            const int r = lrow + i * 16;
            cp16(stA + (uint32_t)(r * PITCH_B + lch * 16),
                 ag + (size_t)r * KTOT + k0 + lch * 8);
        }
        #pragma unroll
        for (int i = 0; i < 8; ++i) {
            const int r = lrow + i * 16;
            cp16(stB + (uint32_t)(r * PITCH_B + lch * 16),
                 bg + (size_t)r * KTOT + k0 + lch * 8);
        }
        CP_COMMIT();
    };

    // prologue: 2 stages in flight
    issue_stage(0);
    issue_stage(1);

    #pragma unroll 1
    for (int kc = 0; kc < NCHUNKS; ++kc) {
        CP_WAIT1();
        __syncthreads();

        if (kc + 2 < NCHUNKS) issue_stage(kc + 2);
        else CP_COMMIT();   // keep group accounting uniform

        const int st = kc % STAGES;
        const uint32_t stA = sbase + (uint32_t)(st * STAGE_B);
        const uint32_t stB = stA + TILEA_B;
        const uint32_t baseA = stA + (uint32_t)rowA * PITCH_B + colA;
        const uint32_t baseB = stB + (uint32_t)rowB * PITCH_B + colB;

        #pragma unroll
        for (int ks = 0; ks < 4; ++ks) {
            const uint32_t kb = (uint32_t)(ks * 32);

            uint32_t a[2][4];
            #pragma unroll
            for (int mi = 0; mi < 2; ++mi)
                ldsm_x4(a[mi][0], a[mi][1], a[mi][2], a[mi][3],
                        baseA + (uint32_t)(mi * 16 * PITCH_B) + kb);

            uint32_t b[8][2];
            #pragma unroll
            for (int np = 0; np < 4; ++np)
                ldsm_x4(b[2 * np][0], b[2 * np][1], b[2 * np + 1][0], b[2 * np + 1][1],
                        baseB + (uint32_t)(np * 16 * PITCH_B) + kb);

            #pragma unroll
            for (int mi = 0; mi < 2; ++mi)
                #pragma unroll
                for (int ni = 0; ni < 8; ++ni)
                    mma_f16(acc[mi][ni], a[mi][0], a[mi][1], a[mi][2], a[mi][3],
                            b[ni][0], b[ni][1]);
        }
    }

    // ---- epilogue: direct float2 stores ----
    #pragma unroll
    for (int mi = 0; mi < 2; ++mi) {
        const int r = m0 + warp_m * 32 + mi * 16 + grp;
        #pragma unroll
        for (int ni = 0; ni < 8; ++ni) {
            const int c = n0 + warp_n * 64 + ni * 8 + tig * 2;
            float2 v0 = make_float2(acc[mi][ni][0], acc[mi][ni][1]);
            float2 v1 = make_float2(acc[mi][ni][2], acc[mi][ni][3]);
            *reinterpret_cast<float2*>(out + (size_t)r * OUT_F + c) = v0;
            *reinterpret_cast<float2*>(out + (size_t)(r + 8) * OUT_F + c) = v1;
        }
    }
}

// ---------------- launch ----------------
extern "C" void kernel_launch(void* const* d_in, const int* in_sizes, int n_in,
                              void* d_out, int out_size) {
    const float* x    = (const float*)d_in[0];
    const float* w1   = (const float*)d_in[1];
    const float* grid = (const float*)d_in[2];
    float* out = (float*)d_out;

    k_prep<<<dim3(OUT_F / 32, IN_F / 32), dim3(32, 32)>>>(grid);
    k_mean<<<1, 1024>>>();
    k_wcvt<<<(OUT_F * IN_F / 4) / 256, 256>>>(w1);
    k_xbasis<<<(BATCH * IN_F / 4) / 256, 256>>>(x);

    cudaFuncSetAttribute(k_gemm, cudaFuncAttributeMaxDynamicSharedMemorySize, SMEM_BYTES);
    k_gemm<<<dim3(OUT_F / BN, BATCH / BM), THREADS, SMEM_BYTES>>>(out);
}